// round 6
// baseline (speedup 1.0000x reference)
#include <cuda_runtime.h>
#include <cuda_fp16.h>
#include <math.h>
#include <stdint.h>

// Problem constants
#define BATCH   32
#define SEQ     2048
#define DMODEL  256
#define HIDDEN  512
#define INNER   1024
#define TOKENS  (BATCH * SEQ)           // 65536
#define NCH     (BATCH * HIDDEN)        // 16384 scan channels
#define NCHUNK  16
#define TCHUNK  (SEQ / NCHUNK)          // 128

// ---------------------------------------------------------------------------
// Scratch (static device memory)
// ---------------------------------------------------------------------------
__device__ float  g_xz   [(size_t)TOKENS * 1024];   // [xh | z] fp32
__device__ float  g_xc   [(size_t)TOKENS * HIDDEN]; // fp32 (scan)
__device__ __half g_xc16 [(size_t)TOKENS * HIDDEN]; // fp16 (GEMM input)
__device__ __half g_x16  [(size_t)TOKENS * DMODEL];
__device__ __half g_gates16[(size_t)TOKENS * 1024];
__device__ __half g_gh16 [(size_t)TOKENS * HIDDEN];
__device__ float  g_y    [(size_t)TOKENS * DMODEL];
__device__ float  g_hs   [(size_t)TOKENS * DMODEL];
__device__ __half g_hs16 [(size_t)TOKENS * DMODEL];
__device__ __half g_u16  [(size_t)TOKENS * INNER];
__device__ float  g_ff   [(size_t)TOKENS * DMODEL];
__device__ float  g_chA  [(size_t)NCH * NCHUNK];
__device__ float  g_chB  [(size_t)NCH * NCHUNK];
__device__ float  g_pref [(size_t)NCH * NCHUNK];
// transposed fp16 weights [N, K]
__device__ __half g_wt_in   [1024 * 256];
__device__ __half g_wt_gates[1024 * 512];
__device__ __half g_wt_out  [256 * 512];
__device__ __half g_wt_f1   [1024 * 256];
__device__ __half g_wt_f2   [256 * 1024];

__device__ __forceinline__ float siluf(float v)     { return v / (1.0f + __expf(-v)); }
__device__ __forceinline__ float sigmoidf_(float v) { return 1.0f / (1.0f + __expf(-v)); }

// ---------------------------------------------------------------------------
// cp.async helpers
// ---------------------------------------------------------------------------
__device__ __forceinline__ void cp_async16(void* smem, const void* gmem) {
    unsigned s = (unsigned)__cvta_generic_to_shared(smem);
    asm volatile("cp.async.cg.shared.global [%0], [%1], 16;" :: "r"(s), "l"(gmem));
}
__device__ __forceinline__ void cp_commit() { asm volatile("cp.async.commit_group;"); }
template<int N> __device__ __forceinline__ void cp_wait() {
    asm volatile("cp.async.wait_group %0;" :: "n"(N));
}

__device__ __forceinline__ void mma_f16(float c[4], const uint32_t a[4], const uint32_t b[2]) {
    asm volatile(
        "mma.sync.aligned.m16n8k16.row.col.f32.f16.f16.f32 "
        "{%0,%1,%2,%3}, {%4,%5,%6,%7}, {%8,%9}, {%0,%1,%2,%3};\n"
        : "+f"(c[0]), "+f"(c[1]), "+f"(c[2]), "+f"(c[3])
        : "r"(a[0]), "r"(a[1]), "r"(a[2]), "r"(a[3]), "r"(b[0]), "r"(b[1]));
}

// ---------------------------------------------------------------------------
// fp16 tensor-core GEMM: C[M,N] = A[M,K] @ Bt[N,K]^T  (A,Bt fp16, acc fp32)
// 128x128 block tile, BK=32, 256 threads, 8 warps (2x4), warp tile 64x32.
// Smem rows padded to 80B (40 fp16): conflict-free direct LDS frag loads.
// EPI: 0=store fp32, 1=+bias fp32, 2=silu(+bias)->fp16, 3=+bias->fp16
// ---------------------------------------------------------------------------
#define HBK 32
#define SROWB 80   // bytes per smem row (64 data + 16 pad)

template<int EPI>
__global__ void __launch_bounds__(256) hgemm(
    const __half* __restrict__ A, const __half* __restrict__ Bt,
    const float* __restrict__ bias,
    float* __restrict__ C, __half* __restrict__ Ch,
    int M, int N, int K)
{
    __shared__ __align__(16) unsigned char As_[2][128 * SROWB];
    __shared__ __align__(16) unsigned char Bs_[2][128 * SROWB];

    const int tid  = threadIdx.x;
    const int warp = tid >> 5;
    const int lane = tid & 31;
    const int g    = lane >> 2;   // 0..7
    const int tg   = lane & 3;    // 0..3

    const int bm = blockIdx.y * 128;
    const int bn = blockIdx.x * 128;
    const int wm = (warp >> 2) * 64;
    const int wn = (warp & 3) * 32;

    // load mapping: row = tid>>1 (0..127), seg = tid&1 (32B each)
    const int lrow = tid >> 1;
    const int lseg = (tid & 1) * 32;      // byte offset within 64B row

    float acc[4][4][4];
    #pragma unroll
    for (int mi = 0; mi < 4; mi++)
        #pragma unroll
        for (int ni = 0; ni < 4; ni++)
            #pragma unroll
            for (int r = 0; r < 4; r++) acc[mi][ni][r] = 0.0f;

    const int KT = K / HBK;
    const __half* Ag = A  + (size_t)(bm + lrow) * K + (lseg >> 1);
    const __half* Bg = Bt + (size_t)(bn + lrow) * K + (lseg >> 1);

    auto load_tile = [&](int kt, int buf) {
        const __half* a = Ag + kt * HBK;
        const __half* b = Bg + kt * HBK;
        unsigned char* as = As_[buf] + lrow * SROWB + lseg;
        unsigned char* bs = Bs_[buf] + lrow * SROWB + lseg;
        cp_async16(as,      a);
        cp_async16(as + 16, a + 8);
        cp_async16(bs,      b);
        cp_async16(bs + 16, b + 8);
        cp_commit();
    };

    load_tile(0, 0);

    for (int kt = 0; kt < KT; kt++) {
        const int buf = kt & 1;
        if (kt + 1 < KT) {
            load_tile(kt + 1, buf ^ 1);
            cp_wait<1>();
        } else {
            cp_wait<0>();
        }
        __syncthreads();

        const unsigned char* as = As_[buf];
        const unsigned char* bs = Bs_[buf];
        #pragma unroll
        for (int ks = 0; ks < 2; ks++) {
            const int kb = ks * 32 + tg * 4;   // byte offset of k pair
            uint32_t af[4][4];
            #pragma unroll
            for (int mi = 0; mi < 4; mi++) {
                const int r0 = wm + mi * 16 + g;
                const unsigned char* p = as + r0 * SROWB + kb;
                af[mi][0] = *reinterpret_cast<const uint32_t*>(p);
                af[mi][1] = *reinterpret_cast<const uint32_t*>(p + 8 * SROWB);
                af[mi][2] = *reinterpret_cast<const uint32_t*>(p + 16);
                af[mi][3] = *reinterpret_cast<const uint32_t*>(p + 8 * SROWB + 16);
            }
            uint32_t bf[4][2];
            #pragma unroll
            for (int ni = 0; ni < 4; ni++) {
                const int r0 = wn + ni * 8 + g;
                const unsigned char* p = bs + r0 * SROWB + kb;
                bf[ni][0] = *reinterpret_cast<const uint32_t*>(p);
                bf[ni][1] = *reinterpret_cast<const uint32_t*>(p + 16);
            }
            #pragma unroll
            for (int mi = 0; mi < 4; mi++)
                #pragma unroll
                for (int ni = 0; ni < 4; ni++)
                    mma_f16(acc[mi][ni], af[mi], bf[ni]);
        }
        __syncthreads();
    }

    // epilogue
    #pragma unroll
    for (int mi = 0; mi < 4; mi++) {
        const int r0 = bm + wm + mi * 16 + g;
        #pragma unroll
        for (int ni = 0; ni < 4; ni++) {
            const int col = bn + wn + ni * 8 + tg * 2;
            float b0 = 0.f, b1 = 0.f;
            if (EPI >= 1) { b0 = bias[col]; b1 = bias[col + 1]; }
            float v0 = acc[mi][ni][0] + b0;
            float v1 = acc[mi][ni][1] + b1;
            float v2 = acc[mi][ni][2] + b0;
            float v3 = acc[mi][ni][3] + b1;
            if (EPI == 2) { v0 = siluf(v0); v1 = siluf(v1); v2 = siluf(v2); v3 = siluf(v3); }
            if (EPI <= 1) {
                *reinterpret_cast<float2*>(C + (size_t)r0 * N + col)       = make_float2(v0, v1);
                *reinterpret_cast<float2*>(C + (size_t)(r0 + 8) * N + col) = make_float2(v2, v3);
            } else {
                *reinterpret_cast<__half2*>(Ch + (size_t)r0 * N + col)       = __floats2half2_rn(v0, v1);
                *reinterpret_cast<__half2*>(Ch + (size_t)(r0 + 8) * N + col) = __floats2half2_rn(v2, v3);
            }
        }
    }
}

// ---------------------------------------------------------------------------
// Weight transpose + fp32->fp16: out[C,R] = (half)in[R,C]
// ---------------------------------------------------------------------------
__global__ void transpose_cvt_k(const float* __restrict__ in, __half* __restrict__ out,
                                int R, int C)
{
    __shared__ float t[32][33];
    const int c0 = blockIdx.x * 32, r0 = blockIdx.y * 32;
    const int x = threadIdx.x, y = threadIdx.y;
    #pragma unroll
    for (int i = 0; i < 32; i += 8)
        t[y + i][x] = in[(size_t)(r0 + y + i) * C + c0 + x];
    __syncthreads();
    #pragma unroll
    for (int i = 0; i < 32; i += 8)
        out[(size_t)(c0 + y + i) * R + r0 + x] = __float2half(t[x][y + i]);
}

// x fp32 -> fp16
__global__ void cvt_x_k(const float* __restrict__ in, __half* __restrict__ out, int n4)
{
    int i = blockIdx.x * blockDim.x + threadIdx.x;
    if (i >= n4) return;
    float4 v = reinterpret_cast<const float4*>(in)[i];
    __half2 lo = __floats2half2_rn(v.x, v.y);
    __half2 hi = __floats2half2_rn(v.z, v.w);
    reinterpret_cast<uint2*>(out)[i] =
        make_uint2(*reinterpret_cast<uint32_t*>(&lo), *reinterpret_cast<uint32_t*>(&hi));
}

// ---------------------------------------------------------------------------
// Depthwise causal conv (K=4) + SiLU; writes xc fp32 and xc16 fp16
// ---------------------------------------------------------------------------
__global__ void conv_silu_k(const float* __restrict__ xz,
                            const float* __restrict__ cw,
                            const float* __restrict__ cb,
                            float* __restrict__ xc,
                            __half* __restrict__ xc16)
{
    int idx = blockIdx.x * blockDim.x + threadIdx.x;
    if (idx >= TOKENS * (HIDDEN / 4)) return;
    int h4  = idx & 127;
    int tok = idx >> 7;
    int t   = tok & (SEQ - 1);
    int h   = h4 * 4;

    const float* row = xz + (size_t)tok * 1024 + h;
    float4 c0 = *reinterpret_cast<const float4*>(row);
    float4 c1 = (t >= 1) ? *reinterpret_cast<const float4*>(row - 1024) : make_float4(0,0,0,0);
    float4 c2 = (t >= 2) ? *reinterpret_cast<const float4*>(row - 2048) : make_float4(0,0,0,0);
    float4 c3 = (t >= 3) ? *reinterpret_cast<const float4*>(row - 3072) : make_float4(0,0,0,0);

    float4 o;
    float4 bb = *reinterpret_cast<const float4*>(cb + h);
    {
        float4 w = *reinterpret_cast<const float4*>(cw + (size_t)(h + 0) * 4);
        o.x = siluf(fmaf(w.w, c0.x, fmaf(w.z, c1.x, fmaf(w.y, c2.x, fmaf(w.x, c3.x, bb.x)))));
    }
    {
        float4 w = *reinterpret_cast<const float4*>(cw + (size_t)(h + 1) * 4);
        o.y = siluf(fmaf(w.w, c0.y, fmaf(w.z, c1.y, fmaf(w.y, c2.y, fmaf(w.x, c3.y, bb.y)))));
    }
    {
        float4 w = *reinterpret_cast<const float4*>(cw + (size_t)(h + 2) * 4);
        o.z = siluf(fmaf(w.w, c0.z, fmaf(w.z, c1.z, fmaf(w.y, c2.z, fmaf(w.x, c3.z, bb.z)))));
    }
    {
        float4 w = *reinterpret_cast<const float4*>(cw + (size_t)(h + 3) * 4);
        o.w = siluf(fmaf(w.w, c0.w, fmaf(w.z, c1.w, fmaf(w.y, c2.w, fmaf(w.x, c3.w, bb.w)))));
    }
    *reinterpret_cast<float4*>(xc + (size_t)tok * HIDDEN + h) = o;
    __half2 lo = __floats2half2_rn(o.x, o.y);
    __half2 hi = __floats2half2_rn(o.z, o.w);
    *reinterpret_cast<uint2*>(xc16 + (size_t)tok * HIDDEN + h) =
        make_uint2(*reinterpret_cast<uint32_t*>(&lo), *reinterpret_cast<uint32_t*>(&hi));
}

// ---------------------------------------------------------------------------
// Chunked scan (gate nonlinearity fused); gates in fp16
// ---------------------------------------------------------------------------
__device__ __forceinline__ void gate_ab(float rec, float inp, float sp, float xcv,
                                        float& a, float& bp)
{
    a = __expf(-sp * sigmoidf_(rec));
    float beta = sqrtf(1.0f - a * a + 1e-8f) * sigmoidf_(inp);
    bp = beta * xcv;
}

__global__ void scanA_k(const __half* __restrict__ gates,
                        const float* __restrict__ xc,
                        const float* __restrict__ Lambda,
                        float* __restrict__ chA, float* __restrict__ chB)
{
    int id = blockIdx.x * blockDim.x + threadIdx.x;
    if (id >= NCH * NCHUNK) return;
    int c     = id & (NCH - 1);
    int chunk = id >> 14;
    int b = c >> 9;
    int h = c & (HIDDEN - 1);
    float sp = log1pf(__expf(Lambda[h]));

    size_t tok0 = (size_t)b * SEQ + chunk * TCHUNK;
    float A = 1.0f, Bv = 0.0f;
    #pragma unroll 4
    for (int tt = 0; tt < TCHUNK; tt++) {
        size_t tok = tok0 + tt;
        float rec = __half2float(gates[tok * 1024 + h]);
        float inp = __half2float(gates[tok * 1024 + 512 + h]);
        float a, bp;
        gate_ab(rec, inp, sp, xc[tok * HIDDEN + h], a, bp);
        A *= a;
        Bv = fmaf(a, Bv, bp);
    }
    chA[id] = A;
    chB[id] = Bv;
}

__global__ void scanB_k(const float* __restrict__ chA, const float* __restrict__ chB,
                        float* __restrict__ pref)
{
    int c = blockIdx.x * blockDim.x + threadIdx.x;
    if (c >= NCH) return;
    float s = 0.0f;
    #pragma unroll
    for (int chunk = 0; chunk < NCHUNK; chunk++) {
        pref[chunk * NCH + c] = s;
        s = fmaf(chA[chunk * NCH + c], s, chB[chunk * NCH + c]);
    }
}

__global__ void scanC_k(const __half* __restrict__ gates,
                        const float* __restrict__ xc,
                        const float* __restrict__ xz,
                        const float* __restrict__ Lambda,
                        const float* __restrict__ pref,
                        __half* __restrict__ gh16)
{
    int id = blockIdx.x * blockDim.x + threadIdx.x;
    if (id >= NCH * NCHUNK) return;
    int c     = id & (NCH - 1);
    int chunk = id >> 14;
    int b = c >> 9;
    int h = c & (HIDDEN - 1);
    float sp = log1pf(__expf(Lambda[h]));

    size_t tok0 = (size_t)b * SEQ + chunk * TCHUNK;
    float state = pref[id];
    #pragma unroll 4
    for (int tt = 0; tt < TCHUNK; tt++) {
        size_t tok = tok0 + tt;
        float rec = __half2float(gates[tok * 1024 + h]);
        float inp = __half2float(gates[tok * 1024 + 512 + h]);
        float a, bp;
        gate_ab(rec, inp, sp, xc[tok * HIDDEN + h], a, bp);
        state = fmaf(a, state, bp);
        float z = xz[tok * 1024 + 512 + h];
        gh16[tok * HIDDEN + h] = __float2half(state * siluf(z));
    }
}

// ---------------------------------------------------------------------------
// LayerNorm over D=256: out = LN(a + res) * gamma + beta (+ optional fp16 copy)
// ---------------------------------------------------------------------------
template<bool H16>
__global__ void ln_k(const float* __restrict__ a,
                     const float* __restrict__ res,
                     const float* __restrict__ gamma,
                     const float* __restrict__ beta,
                     float* __restrict__ out,
                     __half* __restrict__ out16)
{
    int tok = blockIdx.x;
    int i = threadIdx.x;
    size_t off = (size_t)tok * DMODEL + i;
    float v = a[off] + res[off];

    float s = v, s2 = v * v;
    #pragma unroll
    for (int o = 16; o > 0; o >>= 1) {
        s  += __shfl_xor_sync(0xffffffffu, s,  o);
        s2 += __shfl_xor_sync(0xffffffffu, s2, o);
    }
    __shared__ float sh[2][8];
    int w = i >> 5, l = i & 31;
    if (l == 0) { sh[0][w] = s; sh[1][w] = s2; }
    __syncthreads();
    if (w == 0) {
        float ts  = (l < 8) ? sh[0][l] : 0.0f;
        float ts2 = (l < 8) ? sh[1][l] : 0.0f;
        #pragma unroll
        for (int o = 4; o > 0; o >>= 1) {
            ts  += __shfl_xor_sync(0xffffffffu, ts,  o);
            ts2 += __shfl_xor_sync(0xffffffffu, ts2, o);
        }
        if (l == 0) { sh[0][0] = ts; sh[1][0] = ts2; }
    }
    __syncthreads();
    float mean = sh[0][0] * (1.0f / DMODEL);
    float var  = sh[1][0] * (1.0f / DMODEL) - mean * mean;
    float inv  = rsqrtf(var + 1e-12f);
    float o = (v - mean) * inv * gamma[i] + beta[i];
    out[off] = o;
    if (H16) out16[off] = __float2half(o);
}

// ---------------------------------------------------------------------------
// Host launcher
// ---------------------------------------------------------------------------
extern "C" void kernel_launch(void* const* d_in, const int* in_sizes, int n_in,
                              void* d_out, int out_size)
{
    const float* x      = (const float*)d_in[0];
    const float* w_in   = (const float*)d_in[1];
    const float* conv_w = (const float*)d_in[2];
    const float* conv_b = (const float*)d_in[3];
    const float* w_gate = (const float*)d_in[4];
    const float* b_gate = (const float*)d_in[5];
    const float* Lambda = (const float*)d_in[6];
    const float* w_out  = (const float*)d_in[7];
    const float* ln1_g  = (const float*)d_in[8];
    const float* ln1_b  = (const float*)d_in[9];
    const float* ffn_w1 = (const float*)d_in[10];
    const float* ffn_b1 = (const float*)d_in[11];
    const float* ffn_w2 = (const float*)d_in[12];
    const float* ffn_b2 = (const float*)d_in[13];
    const float* ln2_g  = (const float*)d_in[14];
    const float* ln2_b  = (const float*)d_in[15];
    float* out = (float*)d_out;

    float  *xz, *xc, *y, *hs, *ff, *chA, *chB, *pref;
    __half *x16, *xc16, *gates16, *gh16, *hs16, *u16;
    __half *wt_in, *wt_gates, *wt_out, *wt_f1, *wt_f2;
    cudaGetSymbolAddress((void**)&xz,      g_xz);
    cudaGetSymbolAddress((void**)&xc,      g_xc);
    cudaGetSymbolAddress((void**)&xc16,    g_xc16);
    cudaGetSymbolAddress((void**)&x16,     g_x16);
    cudaGetSymbolAddress((void**)&gates16, g_gates16);
    cudaGetSymbolAddress((void**)&gh16,    g_gh16);
    cudaGetSymbolAddress((void**)&y,       g_y);
    cudaGetSymbolAddress((void**)&hs,      g_hs);
    cudaGetSymbolAddress((void**)&hs16,    g_hs16);
    cudaGetSymbolAddress((void**)&u16,     g_u16);
    cudaGetSymbolAddress((void**)&ff,      g_ff);
    cudaGetSymbolAddress((void**)&chA,     g_chA);
    cudaGetSymbolAddress((void**)&chB,     g_chB);
    cudaGetSymbolAddress((void**)&pref,    g_pref);
    cudaGetSymbolAddress((void**)&wt_in,    g_wt_in);
    cudaGetSymbolAddress((void**)&wt_gates, g_wt_gates);
    cudaGetSymbolAddress((void**)&wt_out,   g_wt_out);
    cudaGetSymbolAddress((void**)&wt_f1,    g_wt_f1);
    cudaGetSymbolAddress((void**)&wt_f2,    g_wt_f2);

    const int M = TOKENS;
    dim3 tb(32, 8);

    // 0) weight transpose+convert, x convert
    transpose_cvt_k<<<dim3(1024/32, 256/32),  tb>>>(w_in,   wt_in,    256, 1024);
    transpose_cvt_k<<<dim3(1024/32, 512/32),  tb>>>(w_gate, wt_gates, 512, 1024);
    transpose_cvt_k<<<dim3(256/32,  512/32),  tb>>>(w_out,  wt_out,   512, 256);
    transpose_cvt_k<<<dim3(1024/32, 256/32),  tb>>>(ffn_w1, wt_f1,    256, 1024);
    transpose_cvt_k<<<dim3(256/32, 1024/32),  tb>>>(ffn_w2, wt_f2,   1024, 256);
    cvt_x_k<<<(TOKENS * DMODEL / 4 + 255) / 256, 256>>>(x, x16, TOKENS * DMODEL / 4);

    // 1) xz = x @ w_in            (fp32 out)
    hgemm<0><<<dim3(1024/128, M/128), 256>>>(x16, wt_in, nullptr, xz, nullptr, M, 1024, 256);

    // 2) conv + silu -> xc, xc16
    conv_silu_k<<<(TOKENS * (HIDDEN/4)) / 256, 256>>>(xz, conv_w, conv_b, xc, xc16);

    // 3) gates16 = xc @ w_gates + b_gates   (fp16 out)
    hgemm<3><<<dim3(1024/128, M/128), 256>>>(xc16, wt_gates, b_gate, nullptr, gates16, M, 1024, 512);

    // 4-6) chunked scan -> gh16
    scanA_k<<<(NCH * NCHUNK) / 256, 256>>>(gates16, xc, Lambda, chA, chB);
    scanB_k<<<NCH / 256, 256>>>(chA, chB, pref);
    scanC_k<<<(NCH * NCHUNK) / 256, 256>>>(gates16, xc, xz, Lambda, pref, gh16);

    // 7) y = gh @ w_out           (fp32 out)
    hgemm<0><<<dim3(256/128, M/128), 256>>>(gh16, wt_out, nullptr, y, nullptr, M, 256, 512);

    // 8) hs = LN1(y + x), + fp16 copy
    ln_k<true><<<TOKENS, DMODEL>>>(y, x, ln1_g, ln1_b, hs, hs16);

    // 9) u16 = silu(hs @ ffn_w1 + b1)   (fp16 out)
    hgemm<2><<<dim3(1024/128, M/128), 256>>>(hs16, wt_f1, ffn_b1, nullptr, u16, M, 1024, 256);

    // 10) ff = u @ ffn_w2 + b2    (fp32 out)
    hgemm<1><<<dim3(256/128, M/128), 256>>>(u16, wt_f2, ffn_b2, ff, nullptr, M, 256, 1024);

    // 11) out = LN2(ff + hs)
    ln_k<false><<<TOKENS, DMODEL>>>(ff, hs, ln2_g, ln2_b, out, nullptr);
}